// round 16
// baseline (speedup 1.0000x reference)
#include <cuda_runtime.h>
#include <math.h>

// ---------------- problem constants ----------------
#define NB   2
#define CHN  64
#define HH   156
#define WW   156
#define LL   (HH*WW)        // 24336
#define NL   (NB*LL)        // 48672
#define C16  16
#define NHH  4
#define CSZ  144
#define KCH  169            // chunks per round (LL / CSZ)
#define HBK  128            // hash buckets
#define KIN  576            // 64*9 conv reduction
#define COUT 144            // 16 + 64 + 64 fused conv outputs
#define NCHUNK 96           // ceil(LL/256)

// attention smem layout (float offsets) -- total 70,272 B -> occupancy 2
#define ATF_XNK   2304      // ull[8][36] keys (per tile)
#define ATF_SS    2880      // [144][38]
#define ATF_SF    8352      // [36][148]
#define ATF_YSM   13680     // [36][68]
#define ATF_RMAX  16128
#define ATF_RSUM  16272
#define ATF_RSCL  16416
#define ATF_RED   16560     // [4][144] partial max/sum
#define ATF_KLID  17136     // int [432]
#define ATF_TOT   17568
#define ATF_BYTES (ATF_TOT*4)

// gemm5 dynamic smem layout (ull offsets) -- double buffered, A transposed
#define G5_APAD  146                 // even pad: 16B-aligned rows for all kk
#define G5_ASZ   (32*G5_APAD)        // 4672 ull per A buffer  [kk][row]
#define G5_BSZ   (32*72)             // 2304 ull per B buffer  [kk][jp]
#define G5_BOFF  (2*G5_ASZ)          // 9344
#define G5_INTS  (G5_BOFF + 2*G5_BSZ)// 13952 (ull) -> ints after
#define G5_HS1F  (G5_INTS*2 + 1296)  // float offset of sHs1 [144][67]
#define G5_BYTES ((G5_HS1F + 144*67)*4)   // 155,392 B

typedef unsigned long long ull;

__device__ __forceinline__ ull ffma2(ull a, ull b, ull c) {
    ull d; asm("fma.rn.f32x2 %0, %1, %2, %3;" : "=l"(d) : "l"(a), "l"(b), "l"(c)); return d;
}
__device__ __forceinline__ ull fmul2(ull a, ull b) {
    ull d; asm("mul.rn.f32x2 %0, %1, %2;" : "=l"(d) : "l"(a), "l"(b)); return d;
}
__device__ __forceinline__ ull pack2(float x, float y) {
    ull d; asm("mov.b64 %0, {%1, %2};" : "=l"(d) : "f"(x), "f"(y)); return d;
}
__device__ __forceinline__ float2 unpack2(ull v) {
    float lo, hi; asm("mov.b64 {%0, %1}, %2;" : "=f"(lo), "=f"(hi) : "l"(v));
    float2 r; r.x = lo; r.y = hi; return r;
}

// ---------------- scratch (device globals; no allocations) ----------------
__device__ float d_convout[(size_t)NL*COUT];
__device__ float d_xnu[(size_t)NL*C16];
__device__ float d_Hs[(size_t)NL*144];
__device__ float d_F2u[(size_t)NL*144];
__device__ float d_rets[(size_t)NB*NHH*LL*64];
__device__ float d_bss[(size_t)NB*NHH*LL];
__device__ int   d_codes[NB*NHH*LL];
__device__ int   d_sortidx[NB*NHH*LL];
__device__ int   d_inv[NB*NHH*LL];
__device__ int   d_chunkhist[NB*NHH*NCHUNK*HBK];
__device__ float d_Bconv[KIN*COUT];
__device__ float d_W1t[64*144];
__device__ float d_W2t[144*144];

// ---------------- 1a/1b/1c. weight repack ----------------
__global__ void repack_conv_kernel(const float* __restrict__ wm,
                                   const float* __restrict__ wa,
                                   const float* __restrict__ wf) {
    int t = blockIdx.x*blockDim.x + threadIdx.x;
    if (t < KIN*COUT) {
        int col = t % COUT;
        int row = t / COUT;
        int ci = row / 9, k = row % 9;
        float v;
        if (col < 16)      v = wm[((size_t)(col      *64 + ci))*9 + k];
        else if (col < 80) v = wa[((size_t)((col-16) *64 + ci))*9 + k];
        else               v = wf[((size_t)((col-80) *64 + ci))*9 + k];
        d_Bconv[t] = v;
    }
}
__global__ void repack_w1_kernel(const float* __restrict__ fw1) {
    int t = blockIdx.x*blockDim.x + threadIdx.x;
    if (t < 64*144)  { int e = t / 144, o = t % 144; d_W1t[t] = fw1[o*64  + e]; }
}
__global__ void repack_w2_kernel(const float* __restrict__ fw2) {
    int t = blockIdx.x*blockDim.x + threadIdx.x;
    if (t < 144*144) { int e = t / 144, o = t % 144; d_W2t[t] = fw2[o*144 + e]; }
}

// ---------------- 2. gemm5: 576 thr, 144x144 tile, A-transposed ------------
// mode 0: conv (implicit im2col, Kd=576) -> d_convout, THEN fused fc1
//         (K=64 from smem-stashed cols 80..143, relu + bias) -> d_Hs
// mode 2: fc2  (Kd=144, bias) -> d_F2u
// All accumulation chains ascending-k, single chain per output ->
// bitwise identical to the unfused version.
__global__ void __launch_bounds__(576, 1) gemm5_kernel(int mode, const float* __restrict__ bias,
                                                       const float* __restrict__ xin) {
    const float* A; int lda, Kd; const float* B; float* Cc; int relu;
    if (mode == 0)      { A = nullptr;        lda = 0;   Kd = KIN; B = d_Bconv; Cc = d_convout; relu = 0; }
    else if (mode == 1) { A = d_convout + 80; lda = 144; Kd = 64;  B = d_W1t;   Cc = d_Hs;      relu = 1; }
    else                { A = d_Hs;           lda = 144; Kd = 144; B = d_W2t;   Cc = d_F2u;     relu = 0; }
    const float* cbias = (mode == 0) ? nullptr : bias;   // conv epilogue: no bias

    extern __shared__ ull gsm[];
    ull*   As2  = gsm;                     // [2][32][146] splatted (a,a), kk-major
    ull*   Bs2  = gsm + G5_BOFF;           // [2][32][72] packed col pairs
    int*   sPix = (int*)(gsm + G5_INTS);   // [144]
    int*   sOff = sPix + 144;              // [576]
    int*   sDxy = sOff + 576;              // [576]
    float* sHs1 = (float*)gsm + G5_HS1F;   // [144][67] conv cols 80..143

    int t = threadIdx.x;
    int ty = t / 24, tx = t % 24;          // 24 x 24
    int i0 = ty*6;                         // 6 rows (even -> 16B aligned)
    int rowbase = blockIdx.x * 144;
    int b = rowbase / LL;
    int l0 = rowbase % LL;
    size_t xb = (size_t)b * CHN * LL;

    if (mode == 0) {
        if (t < 144) {
            int l = l0 + t;
            sPix[t] = (l / WW) * 256 + (l % WW);
        }
        {
            int kg = t;
            int ci = kg / 9, k9 = kg % 9;
            int dy = k9 / 3 - 1, dx = k9 % 3 - 1;
            sOff[kg] = ci * LL + dy * WW + dx;
            sDxy[kg] = ((dy + 1) << 8) | (dx + 1);
        }
    }
    __syncthreads();

    int ntiles = (Kd + 31) / 32;
    float areg[8];
    ull   breg[4];

#define G5_LOAD_A(k0_)                                                          \
    if (mode == 0) {                                                            \
        _Pragma("unroll")                                                       \
        for (int it = 0; it < 8; it++) {                                        \
            int idx = t + it*576;              /* < 4608 = 32*144 */            \
            int kk = idx / 144, r = idx - kk*144;                               \
            int kg = (k0_) + kk;                                                \
            int pk = sPix[r], dxy = sDxy[kg];                                   \
            int yy  = (pk >> 8)  + (dxy >> 8)  - 1;                             \
            int xx2 = (pk & 255) + (dxy & 255) - 1;                             \
            float v = 0.f;                                                      \
            if ((unsigned)yy < HH && (unsigned)xx2 < WW)                        \
                v = xin[xb + (size_t)(sOff[kg] + l0 + r)];                      \
            areg[it] = v;                                                       \
        }                                                                       \
    } else {                                                                    \
        _Pragma("unroll")                                                       \
        for (int it = 0; it < 2; it++) {                                        \
            int idx = t + it*576;                                               \
            int q = idx & 7, r = idx >> 3;                                      \
            float4 v = make_float4(0.f,0.f,0.f,0.f);                            \
            if ((k0_) + q*4 < Kd)                                               \
                v = *(const float4*)(A + (size_t)(rowbase + r)*lda + (k0_) + q*4); \
            areg[it*4+0] = v.x; areg[it*4+1] = v.y;                             \
            areg[it*4+2] = v.z; areg[it*4+3] = v.w;                             \
        }                                                                       \
    }

#define G5_LOAD_B(k0_)                                                          \
    _Pragma("unroll")                                                           \
    for (int it = 0; it < 4; it++) {                                            \
        int idx = t + it*576;                                                   \
        int jp = idx % 72, kk = idx / 72;                                       \
        ull v = 0ull;                                                           \
        if ((k0_) + kk < Kd)                                                    \
            v = *(const ull*)(B + (size_t)((k0_)+kk)*144 + jp*2);               \
        breg[it] = v;                                                           \
    }

#define G5_STORE(bufsel)                                                        \
    {                                                                           \
        ull* Ab = As2 + (bufsel)*G5_ASZ;                                        \
        ull* Bb = Bs2 + (bufsel)*G5_BSZ;                                        \
        if (mode == 0) {                                                        \
            _Pragma("unroll")                                                   \
            for (int it = 0; it < 8; it++) {                                    \
                int idx = t + it*576;                                           \
                int kk = idx / 144, r = idx - kk*144;                           \
                Ab[kk*G5_APAD + r] = pack2(areg[it], areg[it]);                 \
            }                                                                   \
        } else {                                                                \
            _Pragma("unroll")                                                   \
            for (int it = 0; it < 2; it++) {                                    \
                int idx = t + it*576;                                           \
                int q = idx & 7, r = idx >> 3;                                  \
                Ab[(q*4+0)*G5_APAD + r] = pack2(areg[it*4+0], areg[it*4+0]);    \
                Ab[(q*4+1)*G5_APAD + r] = pack2(areg[it*4+1], areg[it*4+1]);    \
                Ab[(q*4+2)*G5_APAD + r] = pack2(areg[it*4+2], areg[it*4+2]);    \
                Ab[(q*4+3)*G5_APAD + r] = pack2(areg[it*4+3], areg[it*4+3]);    \
            }                                                                   \
        }                                                                       \
        _Pragma("unroll")                                                       \
        for (int it = 0; it < 4; it++) {                                        \
            int idx = t + it*576;                                               \
            int jp = idx % 72, kk = idx / 72;                                   \
            Bb[kk*72 + jp] = breg[it];                                          \
        }                                                                       \
    }

    // prologue: stage tile 0 into buffer 0
    G5_LOAD_A(0)
    G5_LOAD_B(0)
    G5_STORE(0)
    __syncthreads();

    ull acc[6][3];
#pragma unroll
    for (int r = 0; r < 6; r++)
#pragma unroll
        for (int s = 0; s < 3; s++) acc[r][s] = 0ull;

    for (int kt = 0; kt < ntiles; kt++) {
        int buf = kt & 1;
        bool more = (kt + 1 < ntiles);
        if (more) {
            int k1 = 32*(kt+1);
            G5_LOAD_A(k1)
            G5_LOAD_B(k1)
        }
        {
            const ull* Ab = As2 + buf*G5_ASZ;
            const ull* Bb = Bs2 + buf*G5_BSZ;
#pragma unroll 8
            for (int kk = 0; kk < 32; kk++) {
                const ull* arow = Ab + kk*G5_APAD + i0;
                ulonglong2 a01 = *(const ulonglong2*)(arow);
                ulonglong2 a23 = *(const ulonglong2*)(arow + 2);
                ulonglong2 a45 = *(const ulonglong2*)(arow + 4);
                ulonglong2 b01 = *(const ulonglong2*)(Bb + kk*72 + 2*tx);
                ull        b2  = Bb[kk*72 + 48 + tx];
                ull a2[6] = { a01.x, a01.y, a23.x, a23.y, a45.x, a45.y };
#pragma unroll
                for (int r = 0; r < 6; r++) {
                    acc[r][0] = ffma2(a2[r], b01.x, acc[r][0]);
                    acc[r][1] = ffma2(a2[r], b01.y, acc[r][1]);
                    acc[r][2] = ffma2(a2[r], b2,    acc[r][2]);
                }
            }
        }
        if (more) G5_STORE(buf ^ 1)
        __syncthreads();
    }
#undef G5_LOAD_A
#undef G5_LOAD_B
#undef G5_STORE

    // epilogue: thread's column pairs are {2tx, 2tx+1, 48+tx}
    {
#pragma unroll
        for (int r = 0; r < 6; r++) {
            int row = rowbase + i0 + r;
            float* cbase = Cc + (size_t)row*144;
            int cols[3] = { 4*tx, 96 + 2*tx, 0 };
            (void)cols;
#pragma unroll
            for (int s = 0; s < 3; s++) {
                int col = (s < 2) ? (2*tx + s)*2 : (48 + tx)*2;
                float2 u = unpack2(acc[r][s]);
                if (cbias) {
                    u.x += cbias[col];
                    u.y += cbias[col + 1];
                }
                if (relu) { u.x = fmaxf(u.x, 0.f); u.y = fmaxf(u.y, 0.f); }
                *(float2*)(cbase + col) = u;
            }
        }
    }

    // ---------------- fused fc1 (mode 0 only) ----------------
    if (mode == 0) {
        // stash conv cols 80..143 (this block owns the full rows)
#pragma unroll
        for (int r = 0; r < 6; r++) {
            int row = i0 + r;
            if (tx >= 20) {
                float2 u0 = unpack2(acc[r][0]);
                float2 u1 = unpack2(acc[r][1]);
                float* d = sHs1 + row*67 + (4*tx - 80);
                d[0] = u0.x; d[1] = u0.y; d[2] = u1.x; d[3] = u1.y;
            }
            float2 u2 = unpack2(acc[r][2]);
            float* d2 = sHs1 + row*67 + 16 + 2*tx;
            d2[0] = u2.x; d2[1] = u2.y;
        }
        __syncthreads();

        ull facc[6][3];
#pragma unroll
        for (int r = 0; r < 6; r++)
#pragma unroll
            for (int s = 0; s < 3; s++) facc[r][s] = 0ull;

        for (int kt = 0; kt < 2; kt++) {          // K=64 = 2 tiles of 32
            int k0 = kt*32;
            // stage A (from sHs1) splatted into buffer 0
#pragma unroll
            for (int it = 0; it < 8; it++) {
                int idx = t + it*576;
                int kk = idx / 144, r = idx - kk*144;
                float v = sHs1[r*67 + k0 + kk];
                As2[kk*G5_APAD + r] = pack2(v, v);
            }
            // stage B (W1t)
#pragma unroll
            for (int it = 0; it < 4; it++) {
                int idx = t + it*576;
                int jp = idx % 72, kk = idx / 72;
                Bs2[kk*72 + jp] = *(const ull*)(d_W1t + (size_t)(k0+kk)*144 + jp*2);
            }
            __syncthreads();
#pragma unroll 8
            for (int kk = 0; kk < 32; kk++) {
                const ull* arow = As2 + kk*G5_APAD + i0;
                ulonglong2 a01 = *(const ulonglong2*)(arow);
                ulonglong2 a23 = *(const ulonglong2*)(arow + 2);
                ulonglong2 a45 = *(const ulonglong2*)(arow + 4);
                ulonglong2 b01 = *(const ulonglong2*)(Bs2 + kk*72 + 2*tx);
                ull        b2  = Bs2[kk*72 + 48 + tx];
                ull a2[6] = { a01.x, a01.y, a23.x, a23.y, a45.x, a45.y };
#pragma unroll
                for (int r = 0; r < 6; r++) {
                    facc[r][0] = ffma2(a2[r], b01.x, facc[r][0]);
                    facc[r][1] = ffma2(a2[r], b01.y, facc[r][1]);
                    facc[r][2] = ffma2(a2[r], b2,    facc[r][2]);
                }
            }
            __syncthreads();
        }
        // fc1 epilogue: bias + relu -> d_Hs
#pragma unroll
        for (int r = 0; r < 6; r++) {
            int row = rowbase + i0 + r;
            float* cbase = d_Hs + (size_t)row*144;
#pragma unroll
            for (int s = 0; s < 3; s++) {
                int col = (s < 2) ? (2*tx + s)*2 : (48 + tx)*2;
                float2 u = unpack2(facc[r][s]);
                u.x = fmaxf(u.x + bias[col],     0.f);
                u.y = fmaxf(u.y + bias[col + 1], 0.f);
                *(float2*)(cbase + col) = u;
            }
        }
    }
}

// ---------------- 3. LSH hash as FFMA2 GEMM + argmax (+ fused norm) --------
__global__ void __launch_bounds__(288) hashg_kernel(const float* __restrict__ rot) {
    __shared__ ull   srot[16*64];
    __shared__ float sxv[144*16];
    __shared__ float sbestf[288];
    __shared__ int   sbii[288];

    int t = threadIdx.x;
    int h = blockIdx.y;
    int rowbase = blockIdx.x * 144;
    int b = rowbase / LL;
    int lbase = rowbase % LL;

    for (int idx = t; idx < 1024; idx += 288) {
        int c = idx >> 6, p = idx & 63;
        srot[idx] = *(const ull*)(rot + c*512 + h*128 + 2*p);
    }
    for (int idx = t; idx < 576; idx += 288) {
        int r = idx >> 2, q = idx & 3;
        const float4 v = *(const float4*)(d_convout + (size_t)(rowbase + r)*COUT + 4*q);
        *(float4*)(sxv + r*16 + 4*q) = v;
    }
    __syncthreads();

    // fused norm (one round's blocks only): same math as the old norm_kernel
    if (h == 0 && t < 144) {
        const float* xr = sxv + t*16;
        float vv[16], s = 0.f;
#pragma unroll
        for (int c = 0; c < 16; c++) { vv[c] = xr[c]; s += vv[c]*vv[c]; }
        float inv = 1.f / fmaxf(sqrtf(s), 5e-5f);
        float* dst = d_xnu + (size_t)(rowbase + t)*16;
#pragma unroll
        for (int c = 0; c < 16; c++) dst[c] = vv[c]*inv;
    }

    int r_row = t % 144;
    int half  = t / 144;
    int pbase = half * 32;

    ull xe[16];
#pragma unroll
    for (int c = 0; c < 16; c++) {
        float v = sxv[r_row*16 + c];
        xe[c] = pack2(v, v);
    }

    float best = -1e30f; int bi = 0;
#pragma unroll
    for (int pc = 0; pc < 32; pc += 8) {
        ull acc[8];
#pragma unroll
        for (int u = 0; u < 8; u++) acc[u] = 0ull;
#pragma unroll
        for (int c = 0; c < 16; c++) {
            const ulonglong2* rp = (const ulonglong2*)(srot + c*64 + pbase + pc);
            ulonglong2 r0 = rp[0], r1 = rp[1], r2 = rp[2], r3 = rp[3];
            acc[0] = ffma2(xe[c], r0.x, acc[0]);
            acc[1] = ffma2(xe[c], r0.y, acc[1]);
            acc[2] = ffma2(xe[c], r1.x, acc[2]);
            acc[3] = ffma2(xe[c], r1.y, acc[3]);
            acc[4] = ffma2(xe[c], r2.x, acc[4]);
            acc[5] = ffma2(xe[c], r2.y, acc[5]);
            acc[6] = ffma2(xe[c], r3.x, acc[6]);
            acc[7] = ffma2(xe[c], r3.y, acc[7]);
        }
#pragma unroll
        for (int u = 0; u < 8; u++) {
            float2 f = unpack2(acc[u]);
            int col = 2*(pbase + pc + u);
            if (f.x > best) { best = f.x; bi = col; }
            if (f.y > best) { best = f.y; bi = col + 1; }
        }
    }
    sbestf[half*144 + r_row] = best;
    sbii  [half*144 + r_row] = bi;
    __syncthreads();
    if (t < 144) {
        float b0 = sbestf[t], b1 = sbestf[144 + t];
        int   c0 = sbii[t],   c1 = sbii[144 + t];
        int code = (b1 > b0) ? c1 : c0;
        d_codes[(size_t)(b*NHH + h)*LL + lbase + t] = code;
    }
}

// ---------------- 4-6. stable counting sort per (b,h) ----------------
__global__ void hist_kernel() {
    __shared__ int cnt[HBK];
    int bh = blockIdx.y, chunk = blockIdx.x, t = threadIdx.x;
    if (t < HBK) cnt[t] = 0;
    __syncthreads();
    int l = chunk*256 + t;
    if (l < LL) atomicAdd(&cnt[d_codes[(size_t)bh*LL + l]], 1);
    __syncthreads();
    if (t < HBK) d_chunkhist[((size_t)bh*NCHUNK + chunk)*HBK + t] = cnt[t];
}

__global__ void scan_kernel() {
    int bh = blockIdx.x, bin = threadIdx.x;
    __shared__ int tot[HBK];
    __shared__ int base[HBK];
    int s = 0;
    for (int c = 0; c < NCHUNK; c++) s += d_chunkhist[((size_t)bh*NCHUNK + c)*HBK + bin];
    tot[bin] = s;
    __syncthreads();
    if (bin == 0) {
        int acc = 0;
        for (int i = 0; i < HBK; i++) { base[i] = acc; acc += tot[i]; }
    }
    __syncthreads();
    int run = base[bin];
    for (int c = 0; c < NCHUNK; c++) {
        size_t idx = ((size_t)bh*NCHUNK + c)*HBK + bin;
        int v = d_chunkhist[idx];
        d_chunkhist[idx] = run;
        run += v;
    }
}

__global__ void scatter_kernel() {
    __shared__ int cnt[HBK];
    int bh = blockIdx.y, chunk = blockIdx.x;
    int t = threadIdx.x, warp = t >> 5, lane = t & 31;
    if (t < HBK) cnt[t] = 0;
    __syncthreads();
    int l = chunk*256 + t;
    bool valid = (l < LL);
    int code = valid ? d_codes[(size_t)bh*LL + l] : (HBK + lane);
    int base = 0, rank = 0;
    for (int w = 0; w < 8; w++) {
        if (warp == w) {
            unsigned mask = __match_any_sync(0xffffffffu, code);
            rank = __popc(mask & ((1u << lane) - 1u));
            int leader = __ffs(mask) - 1;
            int lbase = 0;
            if (lane == leader && valid) {
                lbase = cnt[code];
                cnt[code] = lbase + __popc(mask);
            }
            base = __shfl_sync(0xffffffffu, lbase, leader);
        }
        __syncthreads();
    }
    if (valid) {
        int dest = d_chunkhist[((size_t)bh*NCHUNK + chunk)*HBK + code] + base + rank;
        d_sortidx[(size_t)bh*LL + dest] = l;
        d_inv[(size_t)bh*LL + l] = dest;
    }
}

// ---------------- 8. chunked attention (flash, f32x2, tile 36, occ 2) ------
__global__ void __launch_bounds__(288, 2) attn_kernel() {
    extern __shared__ float smf[];
    ull*   xq2  = (ull*)smf;                 // [8][144] packed c-pairs of queries
    ull*   xnk  = (ull*)(smf + ATF_XNK);     // [8][36]  packed c-pairs of keys (per tile)
    float* sS   = smf + ATF_SS;              // [144][38]
    float* sF   = smf + ATF_SF;              // [36][148]
    float* ysm  = smf + ATF_YSM;             // [36][68]
    float* rmax = smf + ATF_RMAX;
    float* rsum = smf + ATF_RSUM;
    float* rscl = smf + ATF_RSCL;
    float* sRed = smf + ATF_RED;             // [4][144]
    int*   klid = (int*)(smf + ATF_KLID);

    int t = threadIdx.x;
    int bid = blockIdx.x;
    int k = bid % KCH;
    int h = (bid / KCH) & 3;
    int b = bid / (KCH*NHH);
    int bh = b*NHH + h;
    const int* sidx = d_sortidx + (size_t)bh*LL;

    for (int j = t; j < 3*CSZ; j += 288) {
        int pos = (k-1)*CSZ + j;
        if (pos < 0) pos += LL; else if (pos >= LL) pos -= LL;
        klid[j] = sidx[pos];
    }
    if (t < 144) { rmax[t] = -1e30f; rsum[t] = 0.f; }
    __syncthreads();

    // stage queries, transposed + c-packed
    for (int idx = t; idx < 576; idx += 288) {
        int i = idx >> 2, q = idx & 3;
        const float4 v = *(const float4*)(d_convout + (size_t)(b*LL + klid[CSZ + i])*COUT + 4*q);
        xq2[(2*q  )*144 + i] = pack2(v.x, v.y);
        xq2[(2*q+1)*144 + i] = pack2(v.z, v.w);
    }

    int i0 = (t >> 4) * 8;                   // PV: 18 groups x 8 rows
    int o0 = (t & 15) * 4;                   // PV: 16 groups x 4 channels
    ull acc0[8], acc1[8];
#pragma unroll
    for (int r = 0; r < 8; r++) { acc0[r] = 0ull; acc1[r] = 0ull; }

    int iT = t / 12, jT = t % 12;            // S microtile 6x3 per thread
    int si0 = iT*6, jl0 = jT*3;
    int r_row = t % 144, half = t / 144;     // softmax mapping

    for (int tt = 0; tt < 12; tt++) {
        int j0 = tt*36;
        __syncthreads();   // prev PV done -> tile buffers reusable
        // ---- stage key tile (transposed + packed) ----
        if (t < 144) {
            int j = t >> 2, q = t & 3;
            const float4 v = *(const float4*)(d_xnu + (size_t)(b*LL + klid[j0 + j])*16 + 4*q);
            xnk[(2*q  )*36 + j] = pack2(v.x, v.y);
            xnk[(2*q+1)*36 + j] = pack2(v.z, v.w);
        }
        // ---- stage V tile ----
        for (int idx = t; idx < 576; idx += 288) {
            int j = idx >> 4, q = idx & 15;
            const float4 v = *(const float4*)(d_convout +
                (size_t)(b*LL + klid[j0 + j])*COUT + 16 + 4*q);
            *(float4*)(ysm + j*68 + 4*q) = v;
        }
        // ---- stage F2u bias tile ----
        for (int idx = t; idx < 1296; idx += 288) {
            int j = idx / 36, q = idx % 36;
            const float4 v = *(const float4*)(d_F2u +
                (size_t)(b*LL + klid[j0 + j])*144 + 4*q);
            *(float4*)(sF + j*148 + 4*q) = v;
        }
        __syncthreads();
        // ---- S pass: 6x3 microtile per thread ----
        {
            ull sa[6][3];
#pragma unroll
            for (int r = 0; r < 6; r++)
#pragma unroll
                for (int s = 0; s < 3; s++) sa[r][s] = 0ull;
#pragma unroll
            for (int c2 = 0; c2 < 8; c2++) {
                ull a2[6], b2[3];
#pragma unroll
                for (int r = 0; r < 6; r++) a2[r] = xq2[c2*144 + si0 + r];
#pragma unroll
                for (int s = 0; s < 3; s++) b2[s] = xnk[c2*36 + jl0 + s];
#pragma unroll
                for (int r = 0; r < 6; r++)
#pragma unroll
                    for (int s = 0; s < 3; s++) sa[r][s] = ffma2(a2[r], b2[s], sa[r][s]);
            }
#pragma unroll
            for (int s = 0; s < 3; s++) {
                const float* fp = sF + (jl0 + s)*148 + si0;
#pragma unroll
                for (int r = 0; r < 6; r++) {
                    float2 u = unpack2(sa[r][s]);
                    sS[(si0+r)*38 + jl0 + s] = u.x + u.y + fp[r];
                }
            }
        }
        __syncthreads();
        // ---- softmax phase A: per-(row,half) partial max over 18 cols ----
        {
            const float* rowp = sS + r_row*38 + half*18;
            float m = -1e30f;
#pragma unroll
            for (int jj = 0; jj < 18; jj++) m = fmaxf(m, rowp[jj]);
            sRed[half*144 + r_row] = m;
        }
        __syncthreads();
        // ---- phase B: exp + partial sum ----
        {
            float mold = rmax[r_row];
            float mtile = fmaxf(sRed[r_row], sRed[144 + r_row]);
            float mnew = fmaxf(mold, mtile);
            float* rowp = sS + r_row*38 + half*18;
            float s = 0.f;
#pragma unroll
            for (int jj = 0; jj < 18; jj++) {
                float e = __expf(rowp[jj] - mnew);
                rowp[jj] = e; s += e;
            }
            sRed[288 + half*144 + r_row] = s;
        }
        __syncthreads();
        // ---- phase C: running stats ----
        if (t < 144) {
            float mold = rmax[t];
            float mtile = fmaxf(sRed[t], sRed[144 + t]);
            float mnew = fmaxf(mold, mtile);
            float s = sRed[288 + t] + sRed[432 + t];
            float sc = __expf(mold - mnew);
            rscl[t] = sc;
            rsum[t] = rsum[t]*sc + s;
            rmax[t] = mnew;
        }
        __syncthreads();
        // ---- rescale + PV ----
#pragma unroll
        for (int r = 0; r < 8; r++) {
            float sc = rscl[i0 + r];
            ull s2 = pack2(sc, sc);
            acc0[r] = fmul2(acc0[r], s2);
            acc1[r] = fmul2(acc1[r], s2);
        }
        for (int jp = 0; jp < 18; jp++) {
            int jl = jp*2;
            ull ya0 = *(const ull*)(ysm +  jl   *68 + o0);
            ull ya1 = *(const ull*)(ysm +  jl   *68 + o0 + 2);
            ull yb0 = *(const ull*)(ysm + (jl+1)*68 + o0);
            ull yb1 = *(const ull*)(ysm + (jl+1)*68 + o0 + 2);
#pragma unroll
            for (int r = 0; r < 8; r++) {
                ull p2 = *(const ull*)(sS + (i0+r)*38 + jl);
                float2 pf = unpack2(p2);
                ull pa = pack2(pf.x, pf.x);
                ull pb = pack2(pf.y, pf.y);
                acc0[r] = ffma2(pa, ya0, acc0[r]);
                acc1[r] = ffma2(pa, ya1, acc1[r]);
                acc0[r] = ffma2(pb, yb0, acc0[r]);
                acc1[r] = ffma2(pb, yb1, acc1[r]);
            }
        }
    }
    // ---- epilogue ----
#pragma unroll
    for (int r = 0; r < 8; r++) {
        int i = i0 + r;
        float inv = 1.f / rsum[i];
        float2 a = unpack2(acc0[r]);
        float2 c = unpack2(acc1[r]);
        float4 o4 = make_float4(a.x*inv, a.y*inv, c.x*inv, c.y*inv);
        *(float4*)(d_rets + ((size_t)bh*LL + (size_t)k*CSZ + i)*64 + o0) = o4;
    }
    if (t < 144)
        d_bss[(size_t)bh*LL + (size_t)k*CSZ + t] = rmax[t] + logf(rsum[t]);
}

// ---------------- 9. combine rounds + residual ----------------
__global__ void combine_kernel(const float* __restrict__ x, float* __restrict__ out) {
    __shared__ float vsm[128*65];
    __shared__ float probs_sm[128][4];
    __shared__ int   s_sm[128][4];
    int t = threadIdx.x;
    int b = blockIdx.y;
    int l0 = blockIdx.x * 128;
    int npx = LL - l0; if (npx > 128) npx = 128;

    for (int p = t; p < npx; p += 256) {
        int l = l0 + p;
        float bsv[4]; int sv[4]; float m = -1e30f;
#pragma unroll
        for (int h = 0; h < 4; h++) {
            int s = d_inv[(size_t)(b*NHH + h)*LL + l];
            sv[h] = s;
            bsv[h] = d_bss[(size_t)(b*NHH + h)*LL + s];
            m = fmaxf(m, bsv[h]);
        }
        float sum = 0.f;
#pragma unroll
        for (int h = 0; h < 4; h++) { bsv[h] = __expf(bsv[h] - m); sum += bsv[h]; }
        float invs = 1.f / sum;
#pragma unroll
        for (int h = 0; h < 4; h++) { probs_sm[p][h] = bsv[h]*invs; s_sm[p][h] = sv[h]; }
    }
    __syncthreads();
    for (int cell = t; cell < npx*64; cell += 256) {
        int co = cell & 63, p = cell >> 6;
        float v = 0.f;
#pragma unroll
        for (int h = 0; h < 4; h++)
            v += probs_sm[p][h] * d_rets[((size_t)(b*NHH + h)*LL + s_sm[p][h])*64 + co];
        vsm[p*65 + co] = v;
    }
    __syncthreads();
    for (int cell = t; cell < 64*128; cell += 256) {
        int p = cell & 127, co = cell >> 7;
        if (p < npx) {
            int l = l0 + p;
            size_t oi = ((size_t)(b*CHN + co))*LL + l;
            out[oi] = vsm[p*65 + co] + x[oi];
        }
    }
}

// ---------------- launcher ----------------
extern "C" void kernel_launch(void* const* d_in, const int* in_sizes, int n_in,
                              void* d_out, int out_size) {
    (void)in_sizes; (void)n_in; (void)out_size;
    const float* x   = (const float*)d_in[0];
    const float* wm  = (const float*)d_in[1];
    const float* wa  = (const float*)d_in[2];
    const float* wf  = (const float*)d_in[3];
    const float* fw1 = (const float*)d_in[4];
    const float* fb1 = (const float*)d_in[5];
    const float* fw2 = (const float*)d_in[6];
    const float* fb2 = (const float*)d_in[7];
    const float* rot = (const float*)d_in[8];
    float* out = (float*)d_out;

    cudaFuncSetAttribute(attn_kernel, cudaFuncAttributeMaxDynamicSharedMemorySize, ATF_BYTES);
    cudaFuncSetAttribute(gemm5_kernel, cudaFuncAttributeMaxDynamicSharedMemorySize, G5_BYTES);

    repack_conv_kernel<<<(KIN*COUT + 255)/256, 256>>>(wm, wa, wf);   // idx 0
    repack_w1_kernel<<<(64*144 + 255)/256, 256>>>(fw1);              // idx 1
    repack_w2_kernel<<<(144*144 + 255)/256, 256>>>(fw2);             // idx 2

    gemm5_kernel<<<NL/144, 576, G5_BYTES>>>(0, fb1, x);              // conv + fused fc1

    dim3 hgrid(NL/144, NHH);
    hashg_kernel<<<hgrid, 288>>>(rot);                               // hash + fused norm

    dim3 sgrid(NCHUNK, NB*NHH);
    hist_kernel<<<sgrid, 256>>>();
    scan_kernel<<<NB*NHH, HBK>>>();
    scatter_kernel<<<sgrid, 256>>>();

    gemm5_kernel<<<NL/144, 576, G5_BYTES>>>(2, fb2, nullptr);        // fc2

    attn_kernel<<<NB*NHH*KCH, 288, ATF_BYTES>>>();

    dim3 cgrid((LL + 127)/128, NB);
    combine_kernel<<<cgrid, 256>>>(x, out);
}

// round 17
// speedup vs baseline: 1.5738x; 1.5738x over previous
#include <cuda_runtime.h>
#include <math.h>

// ---------------- problem constants ----------------
#define NB   2
#define CHN  64
#define HH   156
#define WW   156
#define LL   (HH*WW)        // 24336
#define NL   (NB*LL)        // 48672
#define C16  16
#define NHH  4
#define CSZ  144
#define KCH  169            // chunks per round (LL / CSZ)
#define HBK  128            // hash buckets
#define KIN  576            // 64*9 conv reduction
#define COUT 144            // 16 + 64 + 64 fused conv outputs
#define NCHUNK 96           // ceil(LL/256)

// attention smem layout (float offsets) -- total 70,272 B -> occupancy 2
#define ATF_XNK   2304      // ull[8][36] keys (per tile)
#define ATF_SS    2880      // [144][38]
#define ATF_SF    8352      // [36][148]
#define ATF_YSM   13680     // [36][68]
#define ATF_RMAX  16128
#define ATF_RSUM  16272
#define ATF_RSCL  16416
#define ATF_RED   16560     // [4][144] partial max/sum
#define ATF_KLID  17136     // int [432]
#define ATF_TOT   17568
#define ATF_BYTES (ATF_TOT*4)

// gemm5 dynamic smem layout (ull offsets) -- double buffered, A transposed
#define G5_APAD  146                 // even pad: 16B-aligned rows for all kk
#define G5_ASZ   (32*G5_APAD)        // 4672 ull per A buffer  [kk][row]
#define G5_BSZ   (32*72)             // 2304 ull per B buffer  [kk][jp]
#define G5_BOFF  (2*G5_ASZ)          // 9344
#define G5_INTS  (G5_BOFF + 2*G5_BSZ)// 13952 (ull) -> ints after
#define G5_BYTES (G5_INTS*8 + (144 + 576 + 576)*4)   // 116800

typedef unsigned long long ull;

__device__ __forceinline__ ull ffma2(ull a, ull b, ull c) {
    ull d; asm("fma.rn.f32x2 %0, %1, %2, %3;" : "=l"(d) : "l"(a), "l"(b), "l"(c)); return d;
}
__device__ __forceinline__ ull fmul2(ull a, ull b) {
    ull d; asm("mul.rn.f32x2 %0, %1, %2;" : "=l"(d) : "l"(a), "l"(b)); return d;
}
__device__ __forceinline__ ull pack2(float x, float y) {
    ull d; asm("mov.b64 %0, {%1, %2};" : "=l"(d) : "f"(x), "f"(y)); return d;
}
__device__ __forceinline__ float2 unpack2(ull v) {
    float lo, hi; asm("mov.b64 {%0, %1}, %2;" : "=f"(lo), "=f"(hi) : "l"(v));
    float2 r; r.x = lo; r.y = hi; return r;
}

// ---------------- scratch (device globals; no allocations) ----------------
__device__ float d_convout[(size_t)NL*COUT];
__device__ float d_xnu[(size_t)NL*C16];
__device__ float d_Hs[(size_t)NL*144];
__device__ float d_F2u[(size_t)NL*144];
__device__ float d_rets[(size_t)NB*NHH*LL*64];
__device__ float d_bss[(size_t)NB*NHH*LL];
__device__ int   d_codes[NB*NHH*LL];
__device__ int   d_sortidx[NB*NHH*LL];
__device__ int   d_inv[NB*NHH*LL];
__device__ int   d_chunkhist[NB*NHH*NCHUNK*HBK];
__device__ float d_Bconv[KIN*COUT];
__device__ float d_W1t[64*144];
__device__ float d_W2t[144*144];

// ---------------- 1a/1b/1c. weight repack ----------------
__global__ void repack_conv_kernel(const float* __restrict__ wm,
                                   const float* __restrict__ wa,
                                   const float* __restrict__ wf) {
    int t = blockIdx.x*blockDim.x + threadIdx.x;
    if (t < KIN*COUT) {
        int col = t % COUT;
        int row = t / COUT;
        int ci = row / 9, k = row % 9;
        float v;
        if (col < 16)      v = wm[((size_t)(col      *64 + ci))*9 + k];
        else if (col < 80) v = wa[((size_t)((col-16) *64 + ci))*9 + k];
        else               v = wf[((size_t)((col-80) *64 + ci))*9 + k];
        d_Bconv[t] = v;
    }
}
__global__ void repack_w1_kernel(const float* __restrict__ fw1) {
    int t = blockIdx.x*blockDim.x + threadIdx.x;
    if (t < 64*144)  { int e = t / 144, o = t % 144; d_W1t[t] = fw1[o*64  + e]; }
}
__global__ void repack_w2_kernel(const float* __restrict__ fw2) {
    int t = blockIdx.x*blockDim.x + threadIdx.x;
    if (t < 144*144) { int e = t / 144, o = t % 144; d_W2t[t] = fw2[o*144 + e]; }
}

// ---------------- 2. gemm5: 576 thr, 144x144 tile, A-transposed, LDS.128 ---
// mode 0: conv (implicit im2col, Kd=576) -> d_convout
// mode 1: fc1  (Kd=64, relu+bias)        -> d_Hs
// mode 2: fc2  (Kd=144, bias)            -> d_F2u
// Thread (ty,tx): rows i0=ty*6..+5, column-pairs {2tx, 2tx+1, 48+tx}.
// Accumulation: ascending k, single chain per output -> bitwise identical.
__global__ void __launch_bounds__(576, 1) gemm5_kernel(int mode, const float* __restrict__ bias,
                                                       const float* __restrict__ xin) {
    const float* A; int lda, Kd; const float* B; float* Cc; int relu;
    if (mode == 0)      { A = nullptr;        lda = 0;   Kd = KIN; B = d_Bconv; Cc = d_convout; relu = 0; }
    else if (mode == 1) { A = d_convout + 80; lda = 144; Kd = 64;  B = d_W1t;   Cc = d_Hs;      relu = 1; }
    else                { A = d_Hs;           lda = 144; Kd = 144; B = d_W2t;   Cc = d_F2u;     relu = 0; }

    extern __shared__ ull gsm[];
    ull* As2  = gsm;                       // [2][32][146] splatted (a,a), kk-major
    ull* Bs2  = gsm + G5_BOFF;             // [2][32][72] packed col pairs
    int* sPix = (int*)(gsm + G5_INTS);     // [144]
    int* sOff = sPix + 144;                // [576]
    int* sDxy = sOff + 576;                // [576]

    int t = threadIdx.x;
    int ty = t / 24, tx = t % 24;          // 24 x 24
    int i0 = ty*6;                         // 6 rows (even -> 16B aligned)
    int rowbase = blockIdx.x * 144;
    int b = rowbase / LL;
    int l0 = rowbase % LL;
    size_t xb = (size_t)b * CHN * LL;

    if (mode == 0) {
        if (t < 144) {
            int l = l0 + t;
            sPix[t] = (l / WW) * 256 + (l % WW);
        }
        {
            int kg = t;
            int ci = kg / 9, k9 = kg % 9;
            int dy = k9 / 3 - 1, dx = k9 % 3 - 1;
            sOff[kg] = ci * LL + dy * WW + dx;
            sDxy[kg] = ((dy + 1) << 8) | (dx + 1);
        }
    }
    __syncthreads();

    int ntiles = (Kd + 31) / 32;
    float areg[8];
    ull   breg[4];

#define G5_LOAD_A(k0_)                                                          \
    if (mode == 0) {                                                            \
        _Pragma("unroll")                                                       \
        for (int it = 0; it < 8; it++) {                                        \
            int idx = t + it*576;              /* < 4608 = 32*144 */            \
            int kk = idx / 144, r = idx - kk*144;                               \
            int kg = (k0_) + kk;                                                \
            int pk = sPix[r], dxy = sDxy[kg];                                   \
            int yy  = (pk >> 8)  + (dxy >> 8)  - 1;                             \
            int xx2 = (pk & 255) + (dxy & 255) - 1;                             \
            float v = 0.f;                                                      \
            if ((unsigned)yy < HH && (unsigned)xx2 < WW)                        \
                v = xin[xb + (size_t)(sOff[kg] + l0 + r)];                      \
            areg[it] = v;                                                       \
        }                                                                       \
    } else {                                                                    \
        _Pragma("unroll")                                                       \
        for (int it = 0; it < 2; it++) {                                        \
            int idx = t + it*576;                                               \
            int q = idx & 7, r = idx >> 3;                                      \
            float4 v = make_float4(0.f,0.f,0.f,0.f);                            \
            if ((k0_) + q*4 < Kd)                                               \
                v = *(const float4*)(A + (size_t)(rowbase + r)*lda + (k0_) + q*4); \
            areg[it*4+0] = v.x; areg[it*4+1] = v.y;                             \
            areg[it*4+2] = v.z; areg[it*4+3] = v.w;                             \
        }                                                                       \
    }

#define G5_LOAD_B(k0_)                                                          \
    _Pragma("unroll")                                                           \
    for (int it = 0; it < 4; it++) {                                            \
        int idx = t + it*576;                                                   \
        int jp = idx % 72, kk = idx / 72;                                       \
        ull v = 0ull;                                                           \
        if ((k0_) + kk < Kd)                                                    \
            v = *(const ull*)(B + (size_t)((k0_)+kk)*144 + jp*2);               \
        breg[it] = v;                                                           \
    }

#define G5_STORE(bufsel)                                                        \
    {                                                                           \
        ull* Ab = As2 + (bufsel)*G5_ASZ;                                        \
        ull* Bb = Bs2 + (bufsel)*G5_BSZ;                                        \
        if (mode == 0) {                                                        \
            _Pragma("unroll")                                                   \
            for (int it = 0; it < 8; it++) {                                    \
                int idx = t + it*576;                                           \
                int kk = idx / 144, r = idx - kk*144;                           \
                Ab[kk*G5_APAD + r] = pack2(areg[it], areg[it]);                 \
            }                                                                   \
        } else {                                                                \
            _Pragma("unroll")                                                   \
            for (int it = 0; it < 2; it++) {                                    \
                int idx = t + it*576;                                           \
                int q = idx & 7, r = idx >> 3;                                  \
                Ab[(q*4+0)*G5_APAD + r] = pack2(areg[it*4+0], areg[it*4+0]);    \
                Ab[(q*4+1)*G5_APAD + r] = pack2(areg[it*4+1], areg[it*4+1]);    \
                Ab[(q*4+2)*G5_APAD + r] = pack2(areg[it*4+2], areg[it*4+2]);    \
                Ab[(q*4+3)*G5_APAD + r] = pack2(areg[it*4+3], areg[it*4+3]);    \
            }                                                                   \
        }                                                                       \
        _Pragma("unroll")                                                       \
        for (int it = 0; it < 4; it++) {                                        \
            int idx = t + it*576;                                               \
            int jp = idx % 72, kk = idx / 72;                                   \
            Bb[kk*72 + jp] = breg[it];                                          \
        }                                                                       \
    }

    // prologue: stage tile 0 into buffer 0
    G5_LOAD_A(0)
    G5_LOAD_B(0)
    G5_STORE(0)
    __syncthreads();

    ull acc[6][3];
#pragma unroll
    for (int r = 0; r < 6; r++)
#pragma unroll
        for (int s = 0; s < 3; s++) acc[r][s] = 0ull;

    for (int kt = 0; kt < ntiles; kt++) {
        int buf = kt & 1;
        bool more = (kt + 1 < ntiles);
        if (more) {
            int k1 = 32*(kt+1);
            G5_LOAD_A(k1)
            G5_LOAD_B(k1)
        }
        {
            const ull* Ab = As2 + buf*G5_ASZ;
            const ull* Bb = Bs2 + buf*G5_BSZ;
#pragma unroll 8
            for (int kk = 0; kk < 32; kk++) {
                const ull* arow = Ab + kk*G5_APAD + i0;
                ulonglong2 a01 = *(const ulonglong2*)(arow);
                ulonglong2 a23 = *(const ulonglong2*)(arow + 2);
                ulonglong2 a45 = *(const ulonglong2*)(arow + 4);
                ulonglong2 b01 = *(const ulonglong2*)(Bb + kk*72 + 2*tx);
                ull        b2  = Bb[kk*72 + 48 + tx];
                ull a2[6] = { a01.x, a01.y, a23.x, a23.y, a45.x, a45.y };
#pragma unroll
                for (int r = 0; r < 6; r++) {
                    acc[r][0] = ffma2(a2[r], b01.x, acc[r][0]);
                    acc[r][1] = ffma2(a2[r], b01.y, acc[r][1]);
                    acc[r][2] = ffma2(a2[r], b2,    acc[r][2]);
                }
            }
        }
        if (more) G5_STORE(buf ^ 1)
        __syncthreads();
    }
#undef G5_LOAD_A
#undef G5_LOAD_B
#undef G5_STORE

    // epilogue: thread's column pairs are {2tx, 2tx+1, 48+tx}
    {
        int cp[3] = { 2*tx, 2*tx + 1, 48 + tx };
#pragma unroll
        for (int r = 0; r < 6; r++) {
            int row = rowbase + i0 + r;
            float* cbase = Cc + (size_t)row*144;
#pragma unroll
            for (int s = 0; s < 3; s++) {
                int col = cp[s]*2;
                float2 u = unpack2(acc[r][s]);
                if (bias) {
                    u.x += bias[col];
                    u.y += bias[col + 1];
                }
                if (relu) { u.x = fmaxf(u.x, 0.f); u.y = fmaxf(u.y, 0.f); }
                *(float2*)(cbase + col) = u;
            }
        }
    }
}

// ---------------- 3. LSH hash as FFMA2 GEMM + argmax (+ fused norm) --------
__global__ void __launch_bounds__(288) hashg_kernel(const float* __restrict__ rot) {
    __shared__ ull   srot[16*64];
    __shared__ float sxv[144*16];
    __shared__ float sbestf[288];
    __shared__ int   sbii[288];

    int t = threadIdx.x;
    int h = blockIdx.y;
    int rowbase = blockIdx.x * 144;
    int b = rowbase / LL;
    int lbase = rowbase % LL;

    for (int idx = t; idx < 1024; idx += 288) {
        int c = idx >> 6, p = idx & 63;
        srot[idx] = *(const ull*)(rot + c*512 + h*128 + 2*p);
    }
    for (int idx = t; idx < 576; idx += 288) {
        int r = idx >> 2, q = idx & 3;
        const float4 v = *(const float4*)(d_convout + (size_t)(rowbase + r)*COUT + 4*q);
        *(float4*)(sxv + r*16 + 4*q) = v;
    }
    __syncthreads();

    // fused norm (round-0 blocks only): identical math to the old norm_kernel
    if (h == 0 && t < 144) {
        const float* xr = sxv + t*16;
        float vv[16], s = 0.f;
#pragma unroll
        for (int c = 0; c < 16; c++) { vv[c] = xr[c]; s += vv[c]*vv[c]; }
        float inv = 1.f / fmaxf(sqrtf(s), 5e-5f);
        float* dst = d_xnu + (size_t)(rowbase + t)*16;
#pragma unroll
        for (int c = 0; c < 16; c++) dst[c] = vv[c]*inv;
    }

    int r_row = t % 144;
    int half  = t / 144;
    int pbase = half * 32;

    ull xe[16];
#pragma unroll
    for (int c = 0; c < 16; c++) {
        float v = sxv[r_row*16 + c];
        xe[c] = pack2(v, v);
    }

    float best = -1e30f; int bi = 0;
#pragma unroll
    for (int pc = 0; pc < 32; pc += 8) {
        ull acc[8];
#pragma unroll
        for (int u = 0; u < 8; u++) acc[u] = 0ull;
#pragma unroll
        for (int c = 0; c < 16; c++) {
            const ulonglong2* rp = (const ulonglong2*)(srot + c*64 + pbase + pc);
            ulonglong2 r0 = rp[0], r1 = rp[1], r2 = rp[2], r3 = rp[3];
            acc[0] = ffma2(xe[c], r0.x, acc[0]);
            acc[1] = ffma2(xe[c], r0.y, acc[1]);
            acc[2] = ffma2(xe[c], r1.x, acc[2]);
            acc[3] = ffma2(xe[c], r1.y, acc[3]);
            acc[4] = ffma2(xe[c], r2.x, acc[4]);
            acc[5] = ffma2(xe[c], r2.y, acc[5]);
            acc[6] = ffma2(xe[c], r3.x, acc[6]);
            acc[7] = ffma2(xe[c], r3.y, acc[7]);
        }
#pragma unroll
        for (int u = 0; u < 8; u++) {
            float2 f = unpack2(acc[u]);
            int col = 2*(pbase + pc + u);
            if (f.x > best) { best = f.x; bi = col; }
            if (f.y > best) { best = f.y; bi = col + 1; }
        }
    }
    sbestf[half*144 + r_row] = best;
    sbii  [half*144 + r_row] = bi;
    __syncthreads();
    if (t < 144) {
        float b0 = sbestf[t], b1 = sbestf[144 + t];
        int   c0 = sbii[t],   c1 = sbii[144 + t];
        int code = (b1 > b0) ? c1 : c0;
        d_codes[(size_t)(b*NHH + h)*LL + lbase + t] = code;
    }
}

// ---------------- 4-6. stable counting sort per (b,h) ----------------
__global__ void hist_kernel() {
    __shared__ int cnt[HBK];
    int bh = blockIdx.y, chunk = blockIdx.x, t = threadIdx.x;
    if (t < HBK) cnt[t] = 0;
    __syncthreads();
    int l = chunk*256 + t;
    if (l < LL) atomicAdd(&cnt[d_codes[(size_t)bh*LL + l]], 1);
    __syncthreads();
    if (t < HBK) d_chunkhist[((size_t)bh*NCHUNK + chunk)*HBK + t] = cnt[t];
}

__global__ void scan_kernel() {
    int bh = blockIdx.x, bin = threadIdx.x;
    __shared__ int tot[HBK];
    __shared__ int base[HBK];
    int s = 0;
    for (int c = 0; c < NCHUNK; c++) s += d_chunkhist[((size_t)bh*NCHUNK + c)*HBK + bin];
    tot[bin] = s;
    __syncthreads();
    if (bin == 0) {
        int acc = 0;
        for (int i = 0; i < HBK; i++) { base[i] = acc; acc += tot[i]; }
    }
    __syncthreads();
    int run = base[bin];
    for (int c = 0; c < NCHUNK; c++) {
        size_t idx = ((size_t)bh*NCHUNK + c)*HBK + bin;
        int v = d_chunkhist[idx];
        d_chunkhist[idx] = run;
        run += v;
    }
}

__global__ void scatter_kernel() {
    __shared__ int cnt[HBK];
    int bh = blockIdx.y, chunk = blockIdx.x;
    int t = threadIdx.x, warp = t >> 5, lane = t & 31;
    if (t < HBK) cnt[t] = 0;
    __syncthreads();
    int l = chunk*256 + t;
    bool valid = (l < LL);
    int code = valid ? d_codes[(size_t)bh*LL + l] : (HBK + lane);
    int base = 0, rank = 0;
    for (int w = 0; w < 8; w++) {
        if (warp == w) {
            unsigned mask = __match_any_sync(0xffffffffu, code);
            rank = __popc(mask & ((1u << lane) - 1u));
            int leader = __ffs(mask) - 1;
            int lbase = 0;
            if (lane == leader && valid) {
                lbase = cnt[code];
                cnt[code] = lbase + __popc(mask);
            }
            base = __shfl_sync(0xffffffffu, lbase, leader);
        }
        __syncthreads();
    }
    if (valid) {
        int dest = d_chunkhist[((size_t)bh*NCHUNK + chunk)*HBK + code] + base + rank;
        d_sortidx[(size_t)bh*LL + dest] = l;
        d_inv[(size_t)bh*LL + l] = dest;
    }
}

// ---------------- 8. chunked attention (flash, f32x2, tile 36, occ 2) ------
__global__ void __launch_bounds__(288, 2) attn_kernel() {
    extern __shared__ float smf[];
    ull*   xq2  = (ull*)smf;                 // [8][144] packed c-pairs of queries
    ull*   xnk  = (ull*)(smf + ATF_XNK);     // [8][36]  packed c-pairs of keys (per tile)
    float* sS   = smf + ATF_SS;              // [144][38]
    float* sF   = smf + ATF_SF;              // [36][148]
    float* ysm  = smf + ATF_YSM;             // [36][68]
    float* rmax = smf + ATF_RMAX;
    float* rsum = smf + ATF_RSUM;
    float* rscl = smf + ATF_RSCL;
    float* sRed = smf + ATF_RED;             // [4][144]
    int*   klid = (int*)(smf + ATF_KLID);

    int t = threadIdx.x;
    int bid = blockIdx.x;
    int k = bid % KCH;
    int h = (bid / KCH) & 3;
    int b = bid / (KCH*NHH);
    int bh = b*NHH + h;
    const int* sidx = d_sortidx + (size_t)bh*LL;

    for (int j = t; j < 3*CSZ; j += 288) {
        int pos = (k-1)*CSZ + j;
        if (pos < 0) pos += LL; else if (pos >= LL) pos -= LL;
        klid[j] = sidx[pos];
    }
    if (t < 144) { rmax[t] = -1e30f; rsum[t] = 0.f; }
    __syncthreads();

    // stage queries, transposed + c-packed
    for (int idx = t; idx < 576; idx += 288) {
        int i = idx >> 2, q = idx & 3;
        const float4 v = *(const float4*)(d_convout + (size_t)(b*LL + klid[CSZ + i])*COUT + 4*q);
        xq2[(2*q  )*144 + i] = pack2(v.x, v.y);
        xq2[(2*q+1)*144 + i] = pack2(v.z, v.w);
    }

    int i0 = (t >> 4) * 8;                   // PV: 18 groups x 8 rows
    int o0 = (t & 15) * 4;                   // PV: 16 groups x 4 channels
    ull acc0[8], acc1[8];
#pragma unroll
    for (int r = 0; r < 8; r++) { acc0[r] = 0ull; acc1[r] = 0ull; }

    int iT = t / 12, jT = t % 12;            // S microtile 6x3 per thread
    int si0 = iT*6, jl0 = jT*3;
    int r_row = t % 144, half = t / 144;     // softmax mapping

    for (int tt = 0; tt < 12; tt++) {
        int j0 = tt*36;
        __syncthreads();   // prev PV done -> tile buffers reusable
        // ---- stage key tile (transposed + packed) ----
        if (t < 144) {
            int j = t >> 2, q = t & 3;
            const float4 v = *(const float4*)(d_xnu + (size_t)(b*LL + klid[j0 + j])*16 + 4*q);
            xnk[(2*q  )*36 + j] = pack2(v.x, v.y);
            xnk[(2*q+1)*36 + j] = pack2(v.z, v.w);
        }
        // ---- stage V tile ----
        for (int idx = t; idx < 576; idx += 288) {
            int j = idx >> 4, q = idx & 15;
            const float4 v = *(const float4*)(d_convout +
                (size_t)(b*LL + klid[j0 + j])*COUT + 16 + 4*q);
            *(float4*)(ysm + j*68 + 4*q) = v;
        }
        // ---- stage F2u bias tile ----
        for (int idx = t; idx < 1296; idx += 288) {
            int j = idx / 36, q = idx % 36;
            const float4 v = *(const float4*)(d_F2u +
                (size_t)(b*LL + klid[j0 + j])*144 + 4*q);
            *(float4*)(sF + j*148 + 4*q) = v;
        }
        __syncthreads();
        // ---- S pass: 6x3 microtile per thread ----
        {
            ull sa[6][3];
#pragma unroll
            for (int r = 0; r < 6; r++)
#pragma unroll
                for (int s = 0; s < 3; s++) sa[r][s] = 0ull;
#pragma unroll
            for (int c2 = 0; c2 < 8; c2++) {
                ull a2[6], b2[3];
#pragma unroll
                for (int r = 0; r < 6; r++) a2[r] = xq2[c2*144 + si0 + r];
#pragma unroll
                for (int s = 0; s < 3; s++) b2[s] = xnk[c2*36 + jl0 + s];
#pragma unroll
                for (int r = 0; r < 6; r++)
#pragma unroll
                    for (int s = 0; s < 3; s++) sa[r][s] = ffma2(a2[r], b2[s], sa[r][s]);
            }
#pragma unroll
            for (int s = 0; s < 3; s++) {
                const float* fp = sF + (jl0 + s)*148 + si0;
#pragma unroll
                for (int r = 0; r < 6; r++) {
                    float2 u = unpack2(sa[r][s]);
                    sS[(si0+r)*38 + jl0 + s] = u.x + u.y + fp[r];
                }
            }
        }
        __syncthreads();
        // ---- softmax phase A: per-(row,half) partial max over 18 cols ----
        {
            const float* rowp = sS + r_row*38 + half*18;
            float m = -1e30f;
#pragma unroll
            for (int jj = 0; jj < 18; jj++) m = fmaxf(m, rowp[jj]);
            sRed[half*144 + r_row] = m;
        }
        __syncthreads();
        // ---- phase B: exp + partial sum ----
        {
            float mold = rmax[r_row];
            float mtile = fmaxf(sRed[r_row], sRed[144 + r_row]);
            float mnew = fmaxf(mold, mtile);
            float* rowp = sS + r_row*38 + half*18;
            float s = 0.f;
#pragma unroll
            for (int jj = 0; jj < 18; jj++) {
                float e = __expf(rowp[jj] - mnew);
                rowp[jj] = e; s += e;
            }
            sRed[288 + half*144 + r_row] = s;
        }
        __syncthreads();
        // ---- phase C: running stats ----
        if (t < 144) {
            float mold = rmax[t];
            float mtile = fmaxf(sRed[t], sRed[144 + t]);
            float mnew = fmaxf(mold, mtile);
            float s = sRed[288 + t] + sRed[432 + t];
            float sc = __expf(mold - mnew);
            rscl[t] = sc;
            rsum[t] = rsum[t]*sc + s;
            rmax[t] = mnew;
        }
        __syncthreads();
        // ---- rescale + PV ----
#pragma unroll
        for (int r = 0; r < 8; r++) {
            float sc = rscl[i0 + r];
            ull s2 = pack2(sc, sc);
            acc0[r] = fmul2(acc0[r], s2);
            acc1[r] = fmul2(acc1[r], s2);
        }
        for (int jp = 0; jp < 18; jp++) {
            int jl = jp*2;
            ull ya0 = *(const ull*)(ysm +  jl   *68 + o0);
            ull ya1 = *(const ull*)(ysm +  jl   *68 + o0 + 2);
            ull yb0 = *(const ull*)(ysm + (jl+1)*68 + o0);
            ull yb1 = *(const ull*)(ysm + (jl+1)*68 + o0 + 2);
#pragma unroll
            for (int r = 0; r < 8; r++) {
                ull p2 = *(const ull*)(sS + (i0+r)*38 + jl);
                float2 pf = unpack2(p2);
                ull pa = pack2(pf.x, pf.x);
                ull pb = pack2(pf.y, pf.y);
                acc0[r] = ffma2(pa, ya0, acc0[r]);
                acc1[r] = ffma2(pa, ya1, acc1[r]);
                acc0[r] = ffma2(pb, yb0, acc0[r]);
                acc1[r] = ffma2(pb, yb1, acc1[r]);
            }
        }
    }
    // ---- epilogue ----
#pragma unroll
    for (int r = 0; r < 8; r++) {
        int i = i0 + r;
        float inv = 1.f / rsum[i];
        float2 a = unpack2(acc0[r]);
        float2 c = unpack2(acc1[r]);
        float4 o4 = make_float4(a.x*inv, a.y*inv, c.x*inv, c.y*inv);
        *(float4*)(d_rets + ((size_t)bh*LL + (size_t)k*CSZ + i)*64 + o0) = o4;
    }
    if (t < 144)
        d_bss[(size_t)bh*LL + (size_t)k*CSZ + t] = rmax[t] + logf(rsum[t]);
}

// ---------------- 9. combine rounds + residual ----------------
__global__ void combine_kernel(const float* __restrict__ x, float* __restrict__ out) {
    __shared__ float vsm[128*65];
    __shared__ float probs_sm[128][4];
    __shared__ int   s_sm[128][4];
    int t = threadIdx.x;
    int b = blockIdx.y;
    int l0 = blockIdx.x * 128;
    int npx = LL - l0; if (npx > 128) npx = 128;

    for (int p = t; p < npx; p += 256) {
        int l = l0 + p;
        float bsv[4]; int sv[4]; float m = -1e30f;
#pragma unroll
        for (int h = 0; h < 4; h++) {
            int s = d_inv[(size_t)(b*NHH + h)*LL + l];
            sv[h] = s;
            bsv[h] = d_bss[(size_t)(b*NHH + h)*LL + s];
            m = fmaxf(m, bsv[h]);
        }
        float sum = 0.f;
#pragma unroll
        for (int h = 0; h < 4; h++) { bsv[h] = __expf(bsv[h] - m); sum += bsv[h]; }
        float invs = 1.f / sum;
#pragma unroll
        for (int h = 0; h < 4; h++) { probs_sm[p][h] = bsv[h]*invs; s_sm[p][h] = sv[h]; }
    }
    __syncthreads();
    for (int cell = t; cell < npx*64; cell += 256) {
        int co = cell & 63, p = cell >> 6;
        float v = 0.f;
#pragma unroll
        for (int h = 0; h < 4; h++)
            v += probs_sm[p][h] * d_rets[((size_t)(b*NHH + h)*LL + s_sm[p][h])*64 + co];
        vsm[p*65 + co] = v;
    }
    __syncthreads();
    for (int cell = t; cell < 64*128; cell += 256) {
        int p = cell & 127, co = cell >> 7;
        if (p < npx) {
            int l = l0 + p;
            size_t oi = ((size_t)(b*CHN + co))*LL + l;
            out[oi] = vsm[p*65 + co] + x[oi];
        }
    }
}

// ---------------- launcher ----------------
extern "C" void kernel_launch(void* const* d_in, const int* in_sizes, int n_in,
                              void* d_out, int out_size) {
    (void)in_sizes; (void)n_in; (void)out_size;
    const float* x   = (const float*)d_in[0];
    const float* wm  = (const float*)d_in[1];
    const float* wa  = (const float*)d_in[2];
    const float* wf  = (const float*)d_in[3];
    const float* fw1 = (const float*)d_in[4];
    const float* fb1 = (const float*)d_in[5];
    const float* fw2 = (const float*)d_in[6];
    const float* fb2 = (const float*)d_in[7];
    const float* rot = (const float*)d_in[8];
    float* out = (float*)d_out;

    cudaFuncSetAttribute(attn_kernel, cudaFuncAttributeMaxDynamicSharedMemorySize, ATF_BYTES);
    cudaFuncSetAttribute(gemm5_kernel, cudaFuncAttributeMaxDynamicSharedMemorySize, G5_BYTES);

    repack_conv_kernel<<<(KIN*COUT + 255)/256, 256>>>(wm, wa, wf);   // idx 0
    repack_w1_kernel<<<(64*144 + 255)/256, 256>>>(fw1);              // idx 1
    repack_w2_kernel<<<(144*144 + 255)/256, 256>>>(fw2);             // idx 2

    gemm5_kernel<<<NL/144, 576, G5_BYTES>>>(0, nullptr, x);          // conv

    dim3 hgrid(NL/144, NHH);
    hashg_kernel<<<hgrid, 288>>>(rot);                               // hash + fused norm

    dim3 sgrid(NCHUNK, NB*NHH);
    hist_kernel<<<sgrid, 256>>>();
    scan_kernel<<<NB*NHH, HBK>>>();
    scatter_kernel<<<sgrid, 256>>>();

    gemm5_kernel<<<NL/144, 576, G5_BYTES>>>(1, fb1, nullptr);        // fc1 (relu)
    gemm5_kernel<<<NL/144, 576, G5_BYTES>>>(2, fb2, nullptr);        // fc2

    attn_kernel<<<NB*NHH*KCH, 288, ATF_BYTES>>>();

    dim3 cgrid((LL + 127)/128, NB);
    combine_kernel<<<cgrid, 256>>>(x, out);
}